// round 1
// baseline (speedup 1.0000x reference)
#include <cuda_runtime.h>
#include <math.h>

// Problem constants (fixed shapes from the reference)
#define NN 50000
#define DD 128
#define GG 8
#define GN_EPS 1e-5f

// ---------------- scratch (device globals; no cudaMalloc allowed) ----------
__device__ float g_agg[NN * DD];     // neighbor sum, then normalized in GEMM load
__device__ float g_deg[NN];
__device__ float g_f[NN * DD];       // post-GELU features
__device__ float g_sum[GG * DD];     // per-graph sum of f
__device__ float g_sumsq[GG * DD];   // per-graph sum of f^2
__device__ float g_cnt[GG];
__device__ float g_tmean[GG * DD];   // mean_scale * mean
__device__ float g_tscale[GG * DD];  // 1/sqrt(var+eps)

// ---------------- helpers ----------------
__device__ __forceinline__ void red_add_v4(float* p, float4 v) {
    size_t gp = __cvta_generic_to_global(p);
    asm volatile("red.global.add.v4.f32 [%0], {%1,%2,%3,%4};"
                 :: "l"(gp), "f"(v.x), "f"(v.y), "f"(v.z), "f"(v.w)
                 : "memory");
}

__device__ __forceinline__ float gelu_exact(float v) {
    return 0.5f * v * (1.0f + erff(v * 0.70710678118654752f));
}

// ---------------- K1: zero scratch ----------------
__global__ void kInit() {
    int i = blockIdx.x * blockDim.x + threadIdx.x;
    if (i < NN * (DD / 4))
        ((float4*)g_agg)[i] = make_float4(0.f, 0.f, 0.f, 0.f);
    if (i < NN) g_deg[i] = 0.f;
    if (i < GG * DD) { g_sum[i] = 0.f; g_sumsq[i] = 0.f; }
    if (i < GG) g_cnt[i] = 0.f;
}

// ---------------- K1b: per-graph node counts ----------------
__global__ void kCnt(const int* __restrict__ batch) {
    __shared__ float h[GG];
    if (threadIdx.x < GG) h[threadIdx.x] = 0.f;
    __syncthreads();
    int i = blockIdx.x * blockDim.x + threadIdx.x;
    if (i < NN) atomicAdd(&h[batch[i]], 1.f);
    __syncthreads();
    if (threadIdx.x < GG) atomicAdd(&g_cnt[threadIdx.x], h[threadIdx.x]);
}

// ---------------- K2: edge scatter (one warp per edge) ----------------
__global__ void kScatter(const int* __restrict__ ei, const float* __restrict__ x, int E) {
    int warp = (blockIdx.x * blockDim.x + threadIdx.x) >> 5;
    int lane = threadIdx.x & 31;
    if (warp >= E) return;
    int src = __ldg(ei + warp);
    int dst = __ldg(ei + E + warp);
    float4 v = ((const float4*)x)[(size_t)src * 32 + lane];
    red_add_v4(g_agg + (size_t)dst * DD + lane * 4, v);
    if (lane == 0) atomicAdd(g_deg + dst, 1.0f);
}

// ---------------- K3: fused GEMM [agg/deg | x] @ [Wl;Wr]^T + bl, GELU,
//                  per-graph sum/sumsq accumulation ----------------
// Tile: 64 rows x 128 cols, K=256. 256 threads, thread = (ty rowgroup, tx colgroup)
// micro-tile 8 rows x 4 cols.
#define SB_STRIDE 132   // padded row stride for B' [256][132]
#define SA_STRIDE 260   // padded row stride for A  [64][260]

__global__ void kFused(const float* __restrict__ x,
                       const int* __restrict__ batch,
                       const float* __restrict__ Wl,
                       const float* __restrict__ Wr,
                       const float* __restrict__ bl) {
    extern __shared__ float sm[];
    float* sB   = sm;                      // [256][SB_STRIDE]  B'[k][j]
    float* sA   = sB + 256 * SB_STRIDE;    // [64][SA_STRIDE]   A'[r][k]
    float* sInv = sA + 64 * SA_STRIDE;     // [64] 1/max(deg,1)

    int tid = threadIdx.x;
    int tx = tid & 31;        // column group: cols [4*tx, 4*tx+4)
    int ty = tid >> 5;        // row group:    rows [8*ty, 8*ty+8)
    int row0 = blockIdx.x * 64;

    // Load B' transposed: sB[k][j] = Wl[j*128+k] (k<128) / Wr[j*128+k-128]
    // (coalesced global read; one-time minor smem write conflicts)
    for (int idx = tid; idx < DD * DD; idx += 256) {
        int j = idx >> 7, k = idx & 127;
        float wl = Wl[idx];
        float wr = Wr[idx];
        sB[k * SB_STRIDE + j] = wl;
        sB[(k + 128) * SB_STRIDE + j] = wr;
    }
    // Inverse degree for the tile's rows
    for (int r = tid; r < 64; r += 256) {
        int row = row0 + r;
        sInv[r] = (row < NN) ? (1.0f / fmaxf(g_deg[row], 1.0f)) : 0.0f;
    }
    __syncthreads();

    // Load A tile: [64][256] = [agg*invdeg | x]
    for (int q = tid; q < 64 * 64; q += 256) {
        int r  = q >> 6;      // row in tile
        int c4 = q & 63;      // float4 column (0..63)
        int row = row0 + r;
        float4 v = make_float4(0.f, 0.f, 0.f, 0.f);
        if (row < NN) {
            if (c4 < 32) {
                v = ((const float4*)g_agg)[(size_t)row * 32 + c4];
                float iv = sInv[r];
                v.x *= iv; v.y *= iv; v.z *= iv; v.w *= iv;
            } else {
                v = ((const float4*)x)[(size_t)row * 32 + (c4 - 32)];
            }
        }
        *(float4*)(sA + r * SA_STRIDE + c4 * 4) = v;
    }
    __syncthreads();

    // Main FFMA loop
    float4 acc[8];
#pragma unroll
    for (int r = 0; r < 8; r++) acc[r] = make_float4(0.f, 0.f, 0.f, 0.f);

    const float* aBase = sA + (ty * 8) * SA_STRIDE;
#pragma unroll 8
    for (int k = 0; k < 256; k++) {
        float4 b = *(const float4*)(sB + k * SB_STRIDE + tx * 4);
#pragma unroll
        for (int r = 0; r < 8; r++) {
            float a = aBase[r * SA_STRIDE + k];   // warp-broadcast LDS
            acc[r].x += a * b.x;
            acc[r].y += a * b.y;
            acc[r].z += a * b.z;
            acc[r].w += a * b.w;
        }
    }

    // Epilogue: +bias, GELU, write f, accumulate per-graph sum/sumsq
    float4 bias = ((const float4*)bl)[tx];
    int rbase = row0 + ty * 8;
    bool full = (rbase + 7 < NN);
    bool uniform = false;
    int g0 = 0;
    if (rbase < NN) {
        g0 = __ldg(batch + rbase);
        if (full) uniform = (__ldg(batch + rbase + 7) == g0);  // batch sorted
    }

    float4 s  = make_float4(0.f, 0.f, 0.f, 0.f);
    float4 sq = make_float4(0.f, 0.f, 0.f, 0.f);

#pragma unroll
    for (int r = 0; r < 8; r++) {
        int row = rbase + r;
        if (row >= NN) break;
        float4 f;
        f.x = gelu_exact(acc[r].x + bias.x);
        f.y = gelu_exact(acc[r].y + bias.y);
        f.z = gelu_exact(acc[r].z + bias.z);
        f.w = gelu_exact(acc[r].w + bias.w);
        ((float4*)g_f)[(size_t)row * 32 + tx] = f;
        if (uniform) {
            s.x += f.x; s.y += f.y; s.z += f.z; s.w += f.w;
            sq.x += f.x * f.x; sq.y += f.y * f.y; sq.z += f.z * f.z; sq.w += f.w * f.w;
        } else {
            int g = __ldg(batch + row);
            int base = g * DD + tx * 4;
            atomicAdd(&g_sum[base + 0], f.x);
            atomicAdd(&g_sum[base + 1], f.y);
            atomicAdd(&g_sum[base + 2], f.z);
            atomicAdd(&g_sum[base + 3], f.w);
            atomicAdd(&g_sumsq[base + 0], f.x * f.x);
            atomicAdd(&g_sumsq[base + 1], f.y * f.y);
            atomicAdd(&g_sumsq[base + 2], f.z * f.z);
            atomicAdd(&g_sumsq[base + 3], f.w * f.w);
        }
    }
    if (uniform) {
        red_add_v4(&g_sum[g0 * DD + tx * 4], s);
        red_add_v4(&g_sumsq[g0 * DD + tx * 4], sq);
    }
}

// ---------------- K4: per-(graph,channel) stats ----------------
__global__ void kStats(const float* __restrict__ mean_scale) {
    int i = blockIdx.x * blockDim.x + threadIdx.x;
    if (i >= GG * DD) return;
    int c = i & 127;
    int g = i >> 7;
    float cnt = fmaxf(g_cnt[g], 1.0f);
    float m   = g_sum[i] / cnt;
    float ex2 = g_sumsq[i] / cnt;
    float s   = mean_scale[c];
    // E[(f - s*m)^2] = E[f^2] - (2s - s^2) * m^2
    float var = ex2 - (2.0f * s - s * s) * m * m;
    g_tmean[i]  = s * m;
    g_tscale[i] = rsqrtf(fmaxf(var, 0.0f) + GN_EPS);
}

// ---------------- K5: finalize out = norm(f)*w + b + x ----------------
__global__ void kFinal(const float* __restrict__ x,
                       const int* __restrict__ batch,
                       const float* __restrict__ gw,
                       const float* __restrict__ gb,
                       float* __restrict__ out) {
    int i4 = blockIdx.x * blockDim.x + threadIdx.x;  // over NN*32 float4s
    if (i4 >= NN * 32) return;
    int row = i4 >> 5;
    int c4  = i4 & 31;
    int g = __ldg(batch + row);
    float4 f  = ((const float4*)g_f)[i4];
    float4 xv = ((const float4*)x)[i4];
    float4 tm = ((const float4*)g_tmean)[g * 32 + c4];
    float4 ts = ((const float4*)g_tscale)[g * 32 + c4];
    float4 wv = ((const float4*)gw)[c4];
    float4 bv = ((const float4*)gb)[c4];
    float4 o;
    o.x = (f.x - tm.x) * ts.x * wv.x + bv.x + xv.x;
    o.y = (f.y - tm.y) * ts.y * wv.y + bv.y + xv.y;
    o.z = (f.z - tm.z) * ts.z * wv.z + bv.z + xv.z;
    o.w = (f.w - tm.w) * ts.w * wv.w + bv.w + xv.w;
    ((float4*)out)[i4] = o;
}

// ---------------- launch ----------------
extern "C" void kernel_launch(void* const* d_in, const int* in_sizes, int n_in,
                              void* d_out, int out_size) {
    const float* x     = (const float*)d_in[0];
    const int*   ei    = (const int*)d_in[1];
    const int*   batch = (const int*)d_in[2];
    int E = in_sizes[1] / 2;

    // Input 3 may be the scalar num_graphs; weights follow.
    int wi = (in_sizes[3] == DD * DD) ? 3 : 4;
    const float* Wl = (const float*)d_in[wi + 0];
    const float* bl = (const float*)d_in[wi + 1];
    const float* Wr = (const float*)d_in[wi + 2];
    const float* gw = (const float*)d_in[wi + 3];
    const float* gb = (const float*)d_in[wi + 4];
    const float* ms = (const float*)d_in[wi + 5];
    float* out = (float*)d_out;

    static const int SMEM_FUSED = (256 * SB_STRIDE + 64 * SA_STRIDE + 64) * 4;
    cudaFuncSetAttribute(kFused, cudaFuncAttributeMaxDynamicSharedMemorySize, SMEM_FUSED);

    // K1: zero scratch
    {
        int total = NN * (DD / 4);
        kInit<<<(total + 255) / 256, 256>>>();
    }
    // K1b: graph counts
    kCnt<<<(NN + 255) / 256, 256>>>(batch);
    // K2: scatter
    {
        long long threads = (long long)E * 32;
        kScatter<<<(int)((threads + 255) / 256), 256>>>(ei, x, E);
    }
    // K3: fused GEMM + GELU + stats accumulation
    kFused<<<(NN + 63) / 64, 256, SMEM_FUSED>>>(x, batch, Wl, Wr, bl);
    // K4: stats
    kStats<<<(GG * DD + 255) / 256, 256>>>(ms);
    // K5: finalize
    kFinal<<<(NN * 32 + 255) / 256, 256>>>(x, batch, gw, gb, out);
}

// round 3
// speedup vs baseline: 1.5874x; 1.5874x over previous
#include <cuda_runtime.h>
#include <math.h>
#include <stdint.h>

// Problem constants (fixed shapes from the reference)
#define NN 50000
#define DD 128
#define GG 8
#define GN_EPS 1e-5f
#define MTILE 128

// ---------------- scratch (device globals; no cudaMalloc allowed) ----------
__device__ float g_agg[NN * DD];     // neighbor sum -> scaled + tf32-rounded
__device__ float g_xtf[NN * DD];     // x rounded to tf32
__device__ float g_wt[DD * 256];     // fused weights [n][k0..255] tf32-rounded
__device__ float g_deg[NN];
__device__ float g_f[NN * DD];       // post-GELU features
__device__ float g_sum[GG * DD];
__device__ float g_sumsq[GG * DD];
__device__ float g_cnt[GG];
__device__ float g_tmean[GG * DD];
__device__ float g_tscale[GG * DD];

// ---------------- helpers ----------------
__device__ __forceinline__ uint32_t smem_u32(const void* p) {
    uint32_t a;
    asm("{ .reg .u64 t; cvta.to.shared.u64 t, %1; cvt.u32.u64 %0, t; }" : "=r"(a) : "l"(p));
    return a;
}
__device__ __forceinline__ void red_add_v4(float* p, float4 v) {
    size_t gp = __cvta_generic_to_global(p);
    asm volatile("red.global.add.v4.f32 [%0], {%1,%2,%3,%4};"
                 :: "l"(gp), "f"(v.x), "f"(v.y), "f"(v.z), "f"(v.w) : "memory");
}
__device__ __forceinline__ float gelu_exact(float v) {
    return 0.5f * v * (1.0f + erff(v * 0.70710678118654752f));
}
__device__ __forceinline__ float cvt_tf32(float f) {
    uint32_t u;
    asm("cvt.rna.satfinite.tf32.f32 %0, %1;" : "=r"(u) : "f"(f));
    return __uint_as_float(u);
}
__device__ __forceinline__ float4 cvt_tf32x4(float4 v) {
    return make_float4(cvt_tf32(v.x), cvt_tf32(v.y), cvt_tf32(v.z), cvt_tf32(v.w));
}
__device__ __forceinline__ void cp16(uint32_t dst, const void* src, bool pred) {
    int sz = pred ? 16 : 0;
    asm volatile("cp.async.cg.shared.global [%0], [%1], 16, %2;"
                 :: "r"(dst), "l"(src), "r"(sz) : "memory");
}
__device__ __forceinline__ void cp_commit() {
    asm volatile("cp.async.commit_group;" ::: "memory");
}
template <int N>
__device__ __forceinline__ void cp_wait() {
    asm volatile("cp.async.wait_group %0;" :: "n"(N) : "memory");
}
__device__ __forceinline__ void mma_tf32(float* d, const uint32_t* a, const uint32_t* b) {
    asm volatile("mma.sync.aligned.m16n8k8.row.col.f32.tf32.tf32.f32 "
                 "{%0,%1,%2,%3}, {%4,%5,%6,%7}, {%8,%9}, {%0,%1,%2,%3};"
                 : "+f"(d[0]), "+f"(d[1]), "+f"(d[2]), "+f"(d[3])
                 : "r"(a[0]), "r"(a[1]), "r"(a[2]), "r"(a[3]), "r"(b[0]), "r"(b[1]));
}

// ---------------- K1: zero scratch ----------------
__global__ void kInit() {
    int i = blockIdx.x * blockDim.x + threadIdx.x;
    if (i < NN * (DD / 4))
        ((float4*)g_agg)[i] = make_float4(0.f, 0.f, 0.f, 0.f);
    if (i < NN) g_deg[i] = 0.f;
    if (i < GG * DD) { g_sum[i] = 0.f; g_sumsq[i] = 0.f; }
    if (i < GG) g_cnt[i] = 0.f;
}

// ---------------- K1b: per-graph node counts ----------------
__global__ void kCnt(const int* __restrict__ batch) {
    __shared__ float h[GG];
    if (threadIdx.x < GG) h[threadIdx.x] = 0.f;
    __syncthreads();
    int i = blockIdx.x * blockDim.x + threadIdx.x;
    if (i < NN) atomicAdd(&h[batch[i]], 1.f);
    __syncthreads();
    if (threadIdx.x < GG) atomicAdd(&g_cnt[threadIdx.x], h[threadIdx.x]);
}

// ---------------- K2: edge scatter (one warp per edge) ----------------
__global__ void kScatter(const int* __restrict__ ei, const float* __restrict__ x, int E) {
    int warp = (blockIdx.x * blockDim.x + threadIdx.x) >> 5;
    int lane = threadIdx.x & 31;
    if (warp >= E) return;
    int src = __ldg(ei + warp);
    int dst = __ldg(ei + E + warp);
    float4 v = ((const float4*)x)[(size_t)src * 32 + lane];
    red_add_v4(g_agg + (size_t)dst * DD + lane * 4, v);
    if (lane == 0) atomicAdd(g_deg + dst, 1.0f);
}

// ---------------- K2b: prep A operands (scale agg by 1/deg, tf32-round) ----
__global__ void kPrep(const float* __restrict__ x) {
    int i4 = blockIdx.x * blockDim.x + threadIdx.x;
    if (i4 >= NN * 32) return;
    int row = i4 >> 5;
    float iv = 1.0f / fmaxf(g_deg[row], 1.0f);
    float4 a = ((const float4*)g_agg)[i4];
    a.x *= iv; a.y *= iv; a.z *= iv; a.w *= iv;
    ((float4*)g_agg)[i4] = cvt_tf32x4(a);
    ((float4*)g_xtf)[i4] = cvt_tf32x4(((const float4*)x)[i4]);
}

// ---------------- K2c: fuse + round weights into g_wt[n][0..255] ----------
__global__ void kPrepW(const float* __restrict__ Wl, const float* __restrict__ Wr) {
    int i4 = blockIdx.x * blockDim.x + threadIdx.x;   // over 128*64 float4
    if (i4 >= DD * 64) return;
    int n = i4 >> 6, c4 = i4 & 63;
    float4 v = (c4 < 32) ? ((const float4*)Wl)[n * 32 + c4]
                         : ((const float4*)Wr)[n * 32 + (c4 - 32)];
    ((float4*)g_wt)[i4] = cvt_tf32x4(v);
}

// ---------------- K3: tf32 mma.sync GEMM 128x128 tile, K=256 ---------------
// smem: double-buffered A[128][36], B[128][36] (floats, stride 36 = conflict-free)
#define ASTRIDE 36
#define BUF_BYTES (128 * ASTRIDE * 4)      // 18432
#define SMEM_G (4 * BUF_BYTES)             // A0,A1,B0,B1 = 73728

__global__ void __launch_bounds__(256) kGemm(const float* __restrict__ bl) {
    extern __shared__ char smem[];
    uint32_t sbase = smem_u32(smem);
    int tid = threadIdx.x, wid = tid >> 5, lane = tid & 31;
    int gid = lane >> 2, tidg = lane & 3;
    int wm = wid & 1, wn = wid >> 1;          // warp tile: rows wm*64, cols wn*32
    int row0 = blockIdx.x * MTILE;

    // issue cp.async for K-chunk c into buffer b
    auto issue = [&](int c, int b) {
        const float* Asrc = (c < 4) ? g_agg : g_xtf;
#pragma unroll
        for (int i = 0; i < 4; i++) {
            int idx = i * 256 + tid;
            int m = idx >> 3, c4 = idx & 7;
            int gr = row0 + m;
            bool ok = gr < NN;
            const float4* src = (const float4*)Asrc + (size_t)(ok ? gr : 0) * 32 + (c & 3) * 8 + c4;
            cp16(sbase + b * BUF_BYTES + (m * ASTRIDE + c4 * 4) * 4, src, ok);
        }
#pragma unroll
        for (int i = 0; i < 4; i++) {
            int idx = i * 256 + tid;
            int n = idx >> 3, c4 = idx & 7;
            const float4* src = (const float4*)g_wt + n * 64 + c * 8 + c4;
            cp16(sbase + (2 + b) * BUF_BYTES + (n * ASTRIDE + c4 * 4) * 4, src, true);
        }
        cp_commit();
    };

    float acc[4][4][4];
#pragma unroll
    for (int mf = 0; mf < 4; mf++)
#pragma unroll
        for (int nf = 0; nf < 4; nf++)
#pragma unroll
            for (int i = 0; i < 4; i++) acc[mf][nf][i] = 0.f;

    issue(0, 0);
    for (int c = 0; c < 8; c++) {
        int b = c & 1;
        if (c < 7) issue(c + 1, b ^ 1);
        if (c < 7) cp_wait<1>(); else cp_wait<0>();
        __syncthreads();

        const float* sA = (const float*)(smem + b * BUF_BYTES);
        const float* sB = (const float*)(smem + (2 + b) * BUF_BYTES);
#pragma unroll
        for (int ks = 0; ks < 32; ks += 8) {
            uint32_t a[4][4], bf[4][2];
#pragma unroll
            for (int mf = 0; mf < 4; mf++) {
                int r = wm * 64 + mf * 16 + gid;
                a[mf][0] = __float_as_uint(sA[r * ASTRIDE + ks + tidg]);
                a[mf][1] = __float_as_uint(sA[(r + 8) * ASTRIDE + ks + tidg]);
                a[mf][2] = __float_as_uint(sA[r * ASTRIDE + ks + tidg + 4]);
                a[mf][3] = __float_as_uint(sA[(r + 8) * ASTRIDE + ks + tidg + 4]);
            }
#pragma unroll
            for (int nf = 0; nf < 4; nf++) {
                int n = wn * 32 + nf * 8 + gid;
                bf[nf][0] = __float_as_uint(sB[n * ASTRIDE + ks + tidg]);
                bf[nf][1] = __float_as_uint(sB[n * ASTRIDE + ks + tidg + 4]);
            }
#pragma unroll
            for (int mf = 0; mf < 4; mf++)
#pragma unroll
                for (int nf = 0; nf < 4; nf++)
                    mma_tf32(acc[mf][nf], a[mf], bf[nf]);
        }
        __syncthreads();
    }

    // Epilogue: bias + exact GELU -> g_f
#pragma unroll
    for (int nf = 0; nf < 4; nf++) {
        int col = wn * 32 + nf * 8 + 2 * tidg;
        float2 bv = *(const float2*)(bl + col);
#pragma unroll
        for (int mf = 0; mf < 4; mf++) {
            int r = row0 + wm * 64 + mf * 16 + gid;
            if (r < NN) {
                float2 f;
                f.x = gelu_exact(acc[mf][nf][0] + bv.x);
                f.y = gelu_exact(acc[mf][nf][1] + bv.y);
                *(float2*)(g_f + (size_t)r * DD + col) = f;
            }
            if (r + 8 < NN) {
                float2 f;
                f.x = gelu_exact(acc[mf][nf][2] + bv.x);
                f.y = gelu_exact(acc[mf][nf][3] + bv.y);
                *(float2*)(g_f + (size_t)(r + 8) * DD + col) = f;
            }
        }
    }
}

// ---------------- K3b: per-graph sum/sumsq over g_f ----------------
__global__ void kStatsAcc(const int* __restrict__ batch) {
    int tx = threadIdx.x & 31, ty = threadIdx.x >> 5;
    int rbase = blockIdx.x * 256 + ty * 32;
    if (rbase >= NN) return;
    int rend = min(rbase + 32, NN);
    int g0 = __ldg(batch + rbase);
    bool uni = (__ldg(batch + rend - 1) == g0);
    float4 s = make_float4(0.f, 0.f, 0.f, 0.f);
    float4 q = make_float4(0.f, 0.f, 0.f, 0.f);
    if (uni) {
        for (int r = rbase; r < rend; r++) {
            float4 f = ((const float4*)g_f)[(size_t)r * 32 + tx];
            s.x += f.x; s.y += f.y; s.z += f.z; s.w += f.w;
            q.x += f.x * f.x; q.y += f.y * f.y; q.z += f.z * f.z; q.w += f.w * f.w;
        }
        red_add_v4(&g_sum[g0 * DD + tx * 4], s);
        red_add_v4(&g_sumsq[g0 * DD + tx * 4], q);
    } else {
        int r = rbase;
        while (r < rend) {
            int g = __ldg(batch + r);
            s = make_float4(0.f, 0.f, 0.f, 0.f);
            q = make_float4(0.f, 0.f, 0.f, 0.f);
            while (r < rend && __ldg(batch + r) == g) {
                float4 f = ((const float4*)g_f)[(size_t)r * 32 + tx];
                s.x += f.x; s.y += f.y; s.z += f.z; s.w += f.w;
                q.x += f.x * f.x; q.y += f.y * f.y; q.z += f.z * f.z; q.w += f.w * f.w;
                r++;
            }
            red_add_v4(&g_sum[g * DD + tx * 4], s);
            red_add_v4(&g_sumsq[g * DD + tx * 4], q);
        }
    }
}

// ---------------- K4: per-(graph,channel) stats ----------------
__global__ void kStats(const float* __restrict__ mean_scale) {
    int i = blockIdx.x * blockDim.x + threadIdx.x;
    if (i >= GG * DD) return;
    int c = i & 127;
    int g = i >> 7;
    float cnt = fmaxf(g_cnt[g], 1.0f);
    float m   = g_sum[i] / cnt;
    float ex2 = g_sumsq[i] / cnt;
    float sc  = mean_scale[c];
    float var = ex2 - (2.0f * sc - sc * sc) * m * m;
    g_tmean[i]  = sc * m;
    g_tscale[i] = rsqrtf(fmaxf(var, 0.0f) + GN_EPS);
}

// ---------------- K5: finalize out = norm(f)*w + b + x ----------------
__global__ void kFinal(const float* __restrict__ x,
                       const int* __restrict__ batch,
                       const float* __restrict__ gw,
                       const float* __restrict__ gb,
                       float* __restrict__ out) {
    int i4 = blockIdx.x * blockDim.x + threadIdx.x;
    if (i4 >= NN * 32) return;
    int row = i4 >> 5;
    int c4  = i4 & 31;
    int g = __ldg(batch + row);
    float4 f  = ((const float4*)g_f)[i4];
    float4 xv = ((const float4*)x)[i4];
    float4 tm = ((const float4*)g_tmean)[g * 32 + c4];
    float4 ts = ((const float4*)g_tscale)[g * 32 + c4];
    float4 wv = ((const float4*)gw)[c4];
    float4 bv = ((const float4*)gb)[c4];
    float4 o;
    o.x = (f.x - tm.x) * ts.x * wv.x + bv.x + xv.x;
    o.y = (f.y - tm.y) * ts.y * wv.y + bv.y + xv.y;
    o.z = (f.z - tm.z) * ts.z * wv.z + bv.z + xv.z;
    o.w = (f.w - tm.w) * ts.w * wv.w + bv.w + xv.w;
    ((float4*)out)[i4] = o;
}

// ---------------- launch ----------------
extern "C" void kernel_launch(void* const* d_in, const int* in_sizes, int n_in,
                              void* d_out, int out_size) {
    const float* x     = (const float*)d_in[0];
    const int*   ei    = (const int*)d_in[1];
    const int*   batch = (const int*)d_in[2];
    int E = in_sizes[1] / 2;

    int wi = (in_sizes[3] == DD * DD) ? 3 : 4;
    const float* Wl = (const float*)d_in[wi + 0];
    const float* bl = (const float*)d_in[wi + 1];
    const float* Wr = (const float*)d_in[wi + 2];
    const float* gw = (const float*)d_in[wi + 3];
    const float* gb = (const float*)d_in[wi + 4];
    const float* ms = (const float*)d_in[wi + 5];
    float* out = (float*)d_out;

    cudaFuncSetAttribute(kGemm, cudaFuncAttributeMaxDynamicSharedMemorySize, SMEM_G);

    {
        int total = NN * (DD / 4);
        kInit<<<(total + 255) / 256, 256>>>();
    }
    kCnt<<<(NN + 255) / 256, 256>>>(batch);
    {
        long long threads = (long long)E * 32;
        kScatter<<<(int)((threads + 255) / 256), 256>>>(ei, x, E);
    }
    kPrep<<<(NN * 32 + 255) / 256, 256>>>(x);
    kPrepW<<<(DD * 64 + 255) / 256, 256>>>(Wl, Wr);
    kGemm<<<(NN + MTILE - 1) / MTILE, 256, SMEM_G>>>(bl);
    kStatsAcc<<<(NN + 255) / 256, 256>>>(batch);
    kStats<<<(GG * DD + 255) / 256, 256>>>(ms);
    kFinal<<<(NN * 32 + 255) / 256, 256>>>(x, batch, gw, gb, out);
}